// round 15
// baseline (speedup 1.0000x reference)
#include <cuda_runtime.h>
#include <cuda_fp16.h>
#include <cstdint>
#include <cstddef>

// Problem dims
#define BATCH 512
#define ICAPS 1152
#define DDIM  8
#define JCAPS 10
#define CDIM  16

// Config: BPC=2, 2 CTAs/SM. Build map: q = tid&3, r = tid>>2 (0..127).
#define TPB  512
#define BPC  2
#define ROWS 128
#define NRD  9             // build rounds of 128 rows
#define NRD2 5             // routing rounds of 256 (4 full + 1 half)
#define WRSH 72            // fp16-W smem row stride in floats (single buffer)
#define WSZ  (ROWS * WRSH) // 9216 floats = 36864 B

// Shared layout (float units)
#define OFF_W   0
#define OFF_XH  WSZ                    // x_hat rows ((i>>1)*4 + slot) x 8 u32
#define XH_U32  (576 * 4 * 8)          // 18432 u32 = 73728 B
#define OFF_RED (OFF_XH + XH_U32)      // 27648 : scratch (build 16*4*8 / routing 16*2*17)
#define OFF_TOT (OFF_RED + 560)        // 28208 : [2][16]
#define OFF_ZT  (OFF_TOT + 32)         // 28240 : [2] (+2 pad)
#define OFF_V   (OFF_ZT + 4)           // 28244 : [2][16]
#define OFF_VS  (OFF_V + 32)           // 28276 : [2][16]
#define SMEMF   (OFF_VS + 32)          // 28308 floats = 113232 B  (2 CTAs/SM fit)

typedef unsigned long long u64;

__device__ __half2 g_Wh[JCAPS * ICAPS * CDIM * DDIM / 2];   // fp16 W scratch (2.95 MB)

__device__ __forceinline__ void cp16(float* dst, const void* src) {
    unsigned s = (unsigned)__cvta_generic_to_shared(dst);
    asm volatile("cp.async.cg.shared.global [%0], [%1], 16;" :: "r"(s), "l"(src));
}
__device__ __forceinline__ u64 pack2(float lo, float hi) {
    u64 r; asm("mov.b64 %0, {%1, %2};" : "=l"(r) : "f"(lo), "f"(hi)); return r;
}
__device__ __forceinline__ void unpack2(u64 v, float& lo, float& hi) {
    asm("mov.b64 {%0, %1}, %2;" : "=f"(lo), "=f"(hi) : "l"(v));
}
__device__ __forceinline__ void ffma2(u64& d, u64 a, u64 b) {
    asm("fma.rn.f32x2 %0, %1, %2, %0;" : "+l"(d) : "l"(a), "l"(b));
}
__device__ __forceinline__ unsigned h2_of(u64 acc) {
    float lo, hi; unpack2(acc, lo, hi);
    __half2 h = __floats2half2_rn(lo, hi);
    return *reinterpret_cast<unsigned*>(&h);
}

// ---- Kernel A: W fp32 -> fp16 ----
__global__ void __launch_bounds__(512, 4)
convert_w_kernel(const float* __restrict__ W)
{
    int i = blockIdx.x * 512 + threadIdx.x;   // float4 index, exact cover (368640)
    float4 f = reinterpret_cast<const float4*>(W)[i];
    g_Wh[i * 2 + 0] = __floats2half2_rn(f.x, f.y);
    g_Wh[i * 2 + 1] = __floats2half2_rn(f.z, f.w);
}

// ---- Kernel B: main (2 CTAs/SM) ----
__global__ void __launch_bounds__(TPB, 2)
digitcaps_kernel(const float* __restrict__ x,
                 float* __restrict__ out)
{
    extern __shared__ float sm[];
    unsigned* xhb = reinterpret_cast<unsigned*>(sm + OFF_XH);

    const int tid  = threadIdx.x;
    const int j    = blockIdx.x % JCAPS;
    const int bg   = blockIdx.x / JCAPS;     // batch pair index 0..255
    const int lane = tid & 31;
    const int warp = tid >> 5;

    const int q  = tid & 3;
    const int r  = tid >> 2;               // 0..127
    const int kap = (r >> 1) & 3;          // kappa = (i>>1)&3 (rd*64 == 0 mod 4)

    const __half* Wjh = reinterpret_cast<const __half*>(g_Wh)
                      + (size_t)j * ICAPS * (DDIM * CDIM);
    const float* xg0 = x + ((size_t)bg * BPC + 0) * ICAPS * DDIM;
    const float* xg1 = x + ((size_t)bg * BPC + 1) * ICAPS * DDIM;

    // ---- Prologue: stage fp16 W round 0 (2048 16B chunks, 4/thread) ----
    #pragma unroll
    for (int k = 0; k < 4; k++) {
        int idx = k * TPB + tid;
        cp16(sm + OFF_W + (idx >> 4) * WRSH + (idx & 15) * 4, Wjh + (size_t)idx * 8);
    }
    asm volatile("cp.async.commit_group;");

    u64 S0p[4];                            // iter-0 S: 2 batches x 2 ch-pairs... (b, pair)
    #pragma unroll
    for (int k = 0; k < 4; k++) S0p[k] = 0ull;

    // ---- Build: 9 rounds, single W buffer (co-CTA hides the staging bubble) ----
    #pragma unroll 1
    for (int rd = 0; rd < NRD; rd++) {
        asm volatile("cp.async.wait_group 0;");
        __syncthreads();                   // W[rd] visible

        const int i = rd * ROWS + r;

        const float* px0 = xg0 + (size_t)i * DDIM;
        const float* px1 = xg1 + (size_t)i * DDIM;
        float4 a0 = *reinterpret_cast<const float4*>(px0);
        float4 b0 = *reinterpret_cast<const float4*>(px0 + 4);
        float4 a1 = *reinterpret_cast<const float4*>(px1);
        float4 b1 = *reinterpret_cast<const float4*>(px1 + 4);
        float xv0[8] = {a0.x,a0.y,a0.z,a0.w,b0.x,b0.y,b0.z,b0.w};
        float xv1[8] = {a1.x,a1.y,a1.z,a1.w,b1.x,b1.y,b1.z,b1.w};

        const float* wrow = sm + OFF_W + r * WRSH + q * 2;
        u64 ac0 = 0ull, ac1 = 0ull, ac2 = 0ull, ac3 = 0ull;

        #pragma unroll
        for (int d = 0; d < 8; d++) {
            uint2 u = *reinterpret_cast<const uint2*>(wrow + d * 8);
            __half2 h0 = *reinterpret_cast<__half2*>(&u.x);
            __half2 h1 = *reinterpret_cast<__half2*>(&u.y);
            float2 f0 = __half22float2(h0);
            float2 f1 = __half22float2(h1);
            u64 wa = pack2(f0.x, f0.y);
            u64 wb = pack2(f1.x, f1.y);
            u64 xs0 = pack2(xv0[d], xv0[d]);
            u64 xs1 = pack2(xv1[d], xv1[d]);
            ffma2(ac0, xs0, wa);  ffma2(ac1, xs0, wb);
            ffma2(ac2, xs1, wa);  ffma2(ac3, xs1, wb);
        }

        asm("add.rn.f32x2 %0, %0, %1;" : "+l"(S0p[0]) : "l"(ac0));
        asm("add.rn.f32x2 %0, %0, %1;" : "+l"(S0p[1]) : "l"(ac1));
        asm("add.rn.f32x2 %0, %0, %1;" : "+l"(S0p[2]) : "l"(ac2));
        asm("add.rn.f32x2 %0, %0, %1;" : "+l"(S0p[3]) : "l"(ac3));

        // Store x_hat: row (i>>1)*4 + slot, slot = ((i&1)*2+b)^kap, chunk pp = q^kap
        {
            const unsigned pp = (unsigned)(q ^ kap);
            const int ih = (i >> 1) * 4;
            const int e2 = (r & 1) * 2;
            unsigned row0 = (unsigned)(ih + ((e2 + 0) ^ kap));
            unsigned row1 = (unsigned)(ih + ((e2 + 1) ^ kap));
            *reinterpret_cast<uint2*>(xhb + row0 * 8 + pp * 2) =
                make_uint2(h2_of(ac0), h2_of(ac1));
            *reinterpret_cast<uint2*>(xhb + row1 * 8 + pp * 2) =
                make_uint2(h2_of(ac2), h2_of(ac3));
        }

        __syncthreads();                   // all reads of W[rd] done
        if (rd + 1 < NRD) {
            const __half* wsrc = Wjh + (size_t)(rd + 1) * ROWS * (DDIM * CDIM);
            #pragma unroll
            for (int k = 0; k < 4; k++) {
                int idx = k * TPB + tid;
                cp16(sm + OFF_W + (idx >> 4) * WRSH + (idx & 15) * 4, wsrc + (size_t)idx * 8);
            }
            asm volatile("cp.async.commit_group;");
        }
    }

    // ---- iter-0 reduction (build map; classes = q = lane&3) ----
    float* red = sm + OFF_RED;
    float* tot = sm + OFF_TOT;
    float* zt  = sm + OFF_ZT;
    float* vsm = sm + OFF_V;
    float* vss = sm + OFF_VS;

    {
        float s0[8];                       // [b*4 + cc]
        unpack2(S0p[0], s0[0], s0[1]);
        unpack2(S0p[1], s0[2], s0[3]);
        unpack2(S0p[2], s0[4], s0[5]);
        unpack2(S0p[3], s0[6], s0[7]);
        #pragma unroll
        for (int m = 4; m < 32; m <<= 1)
            #pragma unroll
            for (int e = 0; e < 8; e++)
                s0[e] += __shfl_xor_sync(0xffffffffu, s0[e], m);
        if (lane < 4) {                    // lane == q
            float* rp = red + (warp * 4 + lane) * 8;
            #pragma unroll
            for (int e = 0; e < 8; e++) rp[e] = s0[e];
        }
        __syncthreads();

        if (tid < 32) {
            const int bb = tid & 1, c = tid >> 1;     // c = 0..15
            float s = 0.f;
            #pragma unroll
            for (int w2 = 0; w2 < 16; w2++)
                s += red[(w2 * 4 + (c >> 2)) * 8 + bb * 4 + (c & 3)];
            tot[bb * 16 + c] = s;
        }
        __syncthreads();

        if (tid < BPC) {                   // squash iter 0 (Z = 1152 exactly)
            const int bb = tid;
            const float inv = 1.f / (float)ICAPS;
            float sv[16], n2 = 0.f;
            #pragma unroll
            for (int c = 0; c < 16; c++) {
                sv[c] = tot[bb * 16 + c] * inv;
                n2 += sv[c] * sv[c];
            }
            float nr = sqrtf(n2);
            float coef = (n2 / (1.f + n2)) / (nr + 1e-7f);
            #pragma unroll
            for (int c = 0; c < 16; c++) {
                float vn = coef * sv[c];
                vsm[bb * 16 + c] = vn;
                vss[bb * 16 + c] = vn;     // logits linear in v -> cumulative sum
            }
        }
        __syncthreads();
    }

    // ---- Routing iters 1,2: thread = (b2 = tid&1, r2 = tid>>1 in 0..255) ----
    const int b2  = tid & 1;
    const int r2  = tid >> 1;
    const int kp2 = (r2 >> 1) & 3;         // kappa (rd*128 == 0 mod 4)
    const int sl2 = ((r2 & 1) * 2 + b2) ^ kp2;

    #pragma unroll
    for (int it = 1; it < 3; it++) {
        float S[16];
        #pragma unroll
        for (int c = 0; c < 16; c++) S[c] = 0.f;
        float Zp = 0.f;
        float vv[16];
        #pragma unroll
        for (int c = 0; c < 16; c++) vv[c] = vss[b2 * 16 + c];

        #pragma unroll
        for (int rd = 0; rd < NRD2; rd++) {
            const int i = rd * 256 + r2;
            if (i < ICAPS) {               // last round: warps 0..7 only (warp-aligned)
                const unsigned base = (unsigned)(((i >> 1) * 4 + sl2) * 8);
                float xf[16];
                #pragma unroll
                for (int cc = 0; cc < 4; cc++) {
                    uint2 u = *reinterpret_cast<const uint2*>(xhb + base + ((cc ^ kp2) * 2));
                    __half2 h0 = *reinterpret_cast<__half2*>(&u.x);
                    __half2 h1 = *reinterpret_cast<__half2*>(&u.y);
                    float2 f0 = __half22float2(h0);
                    float2 f1 = __half22float2(h1);
                    xf[cc * 4 + 0] = f0.x; xf[cc * 4 + 1] = f0.y;
                    xf[cc * 4 + 2] = f1.x; xf[cc * 4 + 3] = f1.y;
                }
                float a = 0.f;
                #pragma unroll
                for (int c = 0; c < 16; c++) a = fmaf(vv[c], xf[c], a);
                float e = __expf(a);       // a IS the logit (vsum . x_hat); |a| small
                Zp += e;
                #pragma unroll
                for (int c = 0; c < 16; c++) S[c] = fmaf(e, xf[c], S[c]);
            }
        }

        // warp reduce over r2 lanes (classes b2 = lane&1)
        #pragma unroll
        for (int m = 2; m < 32; m <<= 1) {
            #pragma unroll
            for (int c = 0; c < 16; c++)
                S[c] += __shfl_xor_sync(0xffffffffu, S[c], m);
            Zp += __shfl_xor_sync(0xffffffffu, Zp, m);
        }
        if (lane < 2) {                    // lane == b2
            float* rp = red + (warp * 2 + lane) * 17;
            #pragma unroll
            for (int c = 0; c < 16; c++) rp[c] = S[c];
            rp[16] = Zp;
        }
        __syncthreads();

        if (tid < 32) {
            const int bb = tid & 1, c = tid >> 1;
            float s = 0.f;
            #pragma unroll
            for (int w2 = 0; w2 < 16; w2++)
                s += red[(w2 * 2 + bb) * 17 + c];
            tot[bb * 16 + c] = s;
        } else if (tid < 34) {
            const int bb = tid - 32;
            float z = 0.f;
            #pragma unroll
            for (int w2 = 0; w2 < 16; w2++)
                z += red[(w2 * 2 + bb) * 17 + 16];
            zt[bb] = z;
        }
        __syncthreads();

        if (tid < BPC) {
            const int bb = tid;
            float inv = 1.f / zt[bb];
            float sv[16], n2 = 0.f;
            #pragma unroll
            for (int c = 0; c < 16; c++) {
                sv[c] = tot[bb * 16 + c] * inv;
                n2 += sv[c] * sv[c];
            }
            float nr = sqrtf(n2);
            float coef = (n2 / (1.f + n2)) / (nr + 1e-7f);
            #pragma unroll
            for (int c = 0; c < 16; c++) {
                float vn = coef * sv[c];
                vsm[bb * 16 + c] = vn;
                vss[bb * 16 + c] += vn;
            }
        }
        __syncthreads();
    }

    // ---- Output (B, J, C) ----
    if (tid < 32) {
        const int bb = tid >> 4, c = tid & 15;
        out[((size_t)(bg * BPC + bb) * JCAPS + j) * CDIM + c] = vsm[bb * 16 + c];
    }
}

extern "C" void kernel_launch(void* const* d_in, const int* in_sizes, int n_in,
                              void* d_out, int out_size)
{
    const float* x = (const float*)d_in[0];
    const float* W = (const float*)d_in[1];
    if (n_in >= 2 &&
        in_sizes[0] == JCAPS * ICAPS * DDIM * CDIM &&
        in_sizes[1] == BATCH * ICAPS * DDIM) {
        const float* t = x; x = W; W = t;
    }
    float* out = (float*)d_out;

    convert_w_kernel<<<720, 512>>>(W);

    cudaFuncSetAttribute(digitcaps_kernel,
                         cudaFuncAttributeMaxDynamicSharedMemorySize,
                         SMEMF * (int)sizeof(float));
    dim3 grid((BATCH / BPC) * JCAPS);      // 2560 CTAs, 2 co-resident per SM
    digitcaps_kernel<<<grid, TPB, SMEMF * sizeof(float)>>>(x, out);
}

// round 16
// speedup vs baseline: 1.3152x; 1.3152x over previous
#include <cuda_runtime.h>
#include <cuda_fp16.h>
#include <cstdint>
#include <cstddef>

// Problem dims
#define BATCH 512
#define ICAPS 1152
#define DDIM  8
#define JCAPS 10
#define CDIM  16

// Config. Build map: q = tid&3 (channel-quad), r = tid>>2 (row 0..127); 4 batches/thread.
#define TPB  512
#define BPC  4
#define ROWS 128
#define NRD  9
#define WRSH 72            // fp16-W smem row stride in floats
#define WSZ1 (ROWS * WRSH) // 9216 floats per buffer

// Shared layout (float units)
#define OFF_W   0
#define OFF_XH  (2 * WSZ1)             // x_hat rows (i*4 + b^(i&3)) x 8 u32, chunk-swizzled
#define XH_U32  (ICAPS * BPC * 8)
#define OFF_RED (OFF_XH + XH_U32)
#define OFF_TOT (OFF_RED + 1152)
#define OFF_ZT  (OFF_TOT + 64)
#define OFF_V   (OFF_ZT + 4)
#define OFF_VS  (OFF_V + 64)
#define SMEMF   (OFF_VS + 64)          // 226576 B

typedef unsigned long long u64;

__device__ __half2 g_Wh[JCAPS * ICAPS * CDIM * DDIM / 2];   // fp16 W scratch (2.95 MB)

__device__ __forceinline__ void cp16(float* dst, const void* src) {
    unsigned s = (unsigned)__cvta_generic_to_shared(dst);
    asm volatile("cp.async.cg.shared.global [%0], [%1], 16;" :: "r"(s), "l"(src));
}
__device__ __forceinline__ u64 pack2(float lo, float hi) {
    u64 r; asm("mov.b64 %0, {%1, %2};" : "=l"(r) : "f"(lo), "f"(hi)); return r;
}
__device__ __forceinline__ void unpack2(u64 v, float& lo, float& hi) {
    asm("mov.b64 {%0, %1}, %2;" : "=f"(lo), "=f"(hi) : "l"(v));
}
__device__ __forceinline__ unsigned h2bits(__half2 h) {
    return *reinterpret_cast<unsigned*>(&h);
}

// ---- Kernel A: W fp32 -> fp16 ----
__global__ void __launch_bounds__(512, 4)
convert_w_kernel(const float* __restrict__ W)
{
    int i = blockIdx.x * 512 + threadIdx.x;   // float4 index, exact cover (368640)
    float4 f = reinterpret_cast<const float4*>(W)[i];
    g_Wh[i * 2 + 0] = __floats2half2_rn(f.x, f.y);
    g_Wh[i * 2 + 1] = __floats2half2_rn(f.z, f.w);
}

// ---- Kernel B: main ----
__global__ void __launch_bounds__(TPB, 1)
digitcaps_kernel(const float* __restrict__ x,
                 float* __restrict__ out)
{
    extern __shared__ float sm[];
    unsigned* xhb = reinterpret_cast<unsigned*>(sm + OFF_XH);

    const int tid  = threadIdx.x;
    const int j    = blockIdx.x % JCAPS;
    const int bg   = blockIdx.x / JCAPS;
    const int lane = tid & 31;
    const int warp = tid >> 5;

    const int q  = tid & 3;
    const int r  = tid >> 2;               // 0..127
    const int s3 = r & 3;                  // == i&3 every round

    const __half* Wjh = reinterpret_cast<const __half*>(g_Wh)
                      + (size_t)j * ICAPS * (DDIM * CDIM);
    const float* xg0 = x + ((size_t)bg * BPC + 0) * ICAPS * DDIM;
    const float* xg1 = x + ((size_t)bg * BPC + 1) * ICAPS * DDIM;
    const float* xg2 = x + ((size_t)bg * BPC + 2) * ICAPS * DDIM;
    const float* xg3 = x + ((size_t)bg * BPC + 3) * ICAPS * DDIM;

    // ---- Prologue: stage fp16 W round 0 ----
    #pragma unroll
    for (int k = 0; k < 4; k++) {
        int idx = k * TPB + tid;
        cp16(sm + OFF_W + (idx >> 4) * WRSH + (idx & 15) * 4, Wjh + (size_t)idx * 8);
    }
    asm volatile("cp.async.commit_group;");

    u64 S0p[8];                            // iter-0 S in f32x2 (cross-round, fp32)
    #pragma unroll
    for (int k = 0; k < 8; k++) S0p[k] = 0ull;

    // ---- Build: 9 rounds, double-buffered fp16 W, native HFMA2 (no dequant) ----
    #pragma unroll 1
    for (int rd = 0; rd < NRD; rd++) {
        asm volatile("cp.async.wait_group 0;");
        __syncthreads();                   // W[rd] visible; all past buffer rd-1

        const int i = rd * ROWS + r;

        // x rows for 4 batches (L2-resident LDG.128 x2 each) -> fp16 dup pairs
        const float* px0 = xg0 + (size_t)i * DDIM;
        const float* px1 = xg1 + (size_t)i * DDIM;
        const float* px2 = xg2 + (size_t)i * DDIM;
        const float* px3 = xg3 + (size_t)i * DDIM;
        float4 a0 = *reinterpret_cast<const float4*>(px0);
        float4 b0 = *reinterpret_cast<const float4*>(px0 + 4);
        float4 a1 = *reinterpret_cast<const float4*>(px1);
        float4 b1 = *reinterpret_cast<const float4*>(px1 + 4);
        float4 a2 = *reinterpret_cast<const float4*>(px2);
        float4 b2 = *reinterpret_cast<const float4*>(px2 + 4);
        float4 a3 = *reinterpret_cast<const float4*>(px3);
        float4 b3 = *reinterpret_cast<const float4*>(px3 + 4);
        __half2 xd0[8] = {__float2half2_rn(a0.x), __float2half2_rn(a0.y),
                          __float2half2_rn(a0.z), __float2half2_rn(a0.w),
                          __float2half2_rn(b0.x), __float2half2_rn(b0.y),
                          __float2half2_rn(b0.z), __float2half2_rn(b0.w)};
        __half2 xd1[8] = {__float2half2_rn(a1.x), __float2half2_rn(a1.y),
                          __float2half2_rn(a1.z), __float2half2_rn(a1.w),
                          __float2half2_rn(b1.x), __float2half2_rn(b1.y),
                          __float2half2_rn(b1.z), __float2half2_rn(b1.w)};
        __half2 xd2[8] = {__float2half2_rn(a2.x), __float2half2_rn(a2.y),
                          __float2half2_rn(a2.z), __float2half2_rn(a2.w),
                          __float2half2_rn(b2.x), __float2half2_rn(b2.y),
                          __float2half2_rn(b2.z), __float2half2_rn(b2.w)};
        __half2 xd3[8] = {__float2half2_rn(a3.x), __float2half2_rn(a3.y),
                          __float2half2_rn(a3.z), __float2half2_rn(a3.w),
                          __float2half2_rn(b3.x), __float2half2_rn(b3.y),
                          __float2half2_rn(b3.z), __float2half2_rn(b3.w)};

        if (rd + 1 < NRD) {
            const __half* wsrc = Wjh + (size_t)(rd + 1) * ROWS * (DDIM * CDIM);
            float* wd = sm + OFF_W + ((rd + 1) & 1) * WSZ1;
            #pragma unroll
            for (int k = 0; k < 4; k++) {
                int idx = k * TPB + tid;
                cp16(wd + (idx >> 4) * WRSH + (idx & 15) * 4, wsrc + (size_t)idx * 8);
            }
            asm volatile("cp.async.commit_group;");
        }

        // HFMA2 directly on raw fp16 W (no cvt, no pack)
        const float* wrow = sm + OFF_W + (rd & 1) * WSZ1 + r * WRSH + q * 2;
        __half2 ac[8];
        #pragma unroll
        for (int k = 0; k < 8; k++) ac[k] = __float2half2_rn(0.f);

        #pragma unroll
        for (int d = 0; d < 8; d++) {
            uint2 u = *reinterpret_cast<const uint2*>(wrow + d * 8);
            __half2 w0 = *reinterpret_cast<__half2*>(&u.x);
            __half2 w1 = *reinterpret_cast<__half2*>(&u.y);
            ac[0] = __hfma2(xd0[d], w0, ac[0]);  ac[1] = __hfma2(xd0[d], w1, ac[1]);
            ac[2] = __hfma2(xd1[d], w0, ac[2]);  ac[3] = __hfma2(xd1[d], w1, ac[3]);
            ac[4] = __hfma2(xd2[d], w0, ac[4]);  ac[5] = __hfma2(xd2[d], w1, ac[5]);
            ac[6] = __hfma2(xd3[d], w0, ac[6]);  ac[7] = __hfma2(xd3[d], w1, ac[7]);
        }

        // fold iter-0 sum in fp32 (once per round)
        #pragma unroll
        for (int k = 0; k < 8; k++) {
            float2 f = __half22float2(ac[k]);
            asm("add.rn.f32x2 %0, %0, %1;" : "+l"(S0p[k]) : "l"(pack2(f.x, f.y)));
        }

        // Store x_hat: acc IS the half2 — direct STS, swizzled (row b^s3, chunk q^s3)
        {
            const unsigned wofs = (unsigned)((q ^ s3) * 2);
            #pragma unroll
            for (int b = 0; b < 4; b++) {
                unsigned row = (unsigned)(i * 4 + (b ^ s3));
                *reinterpret_cast<uint2*>(xhb + row * 8 + wofs) =
                    make_uint2(h2bits(ac[b * 2]), h2bits(ac[b * 2 + 1]));
            }
        }
    }

    // ---- iter-0 reduction (build map) ----
    float* red = sm + OFF_RED;
    float* tot = sm + OFF_TOT;
    float* zt  = sm + OFF_ZT;
    float* vsm = sm + OFF_V;
    float* vss = sm + OFF_VS;

    {
        float s0[16];
        #pragma unroll
        for (int b = 0; b < 4; b++) {
            unpack2(S0p[b * 2],     s0[b * 4 + 0], s0[b * 4 + 1]);
            unpack2(S0p[b * 2 + 1], s0[b * 4 + 2], s0[b * 4 + 3]);
        }
        #pragma unroll
        for (int m = 4; m < 32; m <<= 1)
            #pragma unroll
            for (int e = 0; e < 16; e++)
                s0[e] += __shfl_xor_sync(0xffffffffu, s0[e], m);
        if (lane < 4) {                    // lane == q class
            float* rp = red + (warp * 4 + lane) * 16;
            #pragma unroll
            for (int e = 0; e < 16; e++) rp[e] = s0[e];
        }
        __syncthreads();

        if (tid < 64) {
            const int bb = tid & 3, c = tid >> 2;
            float s = 0.f;
            #pragma unroll
            for (int w2 = 0; w2 < 16; w2++)
                s += red[(w2 * 4 + (c >> 2)) * 16 + bb * 4 + (c & 3)];
            tot[bb * 16 + c] = s;
        }
        __syncthreads();

        if (tid < BPC) {                   // squash iter 0 (Z = 1152 exactly)
            const int bb = tid;
            const float inv = 1.f / (float)ICAPS;
            float sv[16], n2 = 0.f;
            #pragma unroll
            for (int c = 0; c < 16; c++) {
                sv[c] = tot[bb * 16 + c] * inv;
                n2 += sv[c] * sv[c];
            }
            float nr = sqrtf(n2);
            float coef = (n2 / (1.f + n2)) / (nr + 1e-7f);
            #pragma unroll
            for (int c = 0; c < 16; c++) {
                float vn = coef * sv[c];
                vsm[bb * 16 + c] = vn;
                vss[bb * 16 + c] = vn;     // logits linear in v -> cumulative sum
            }
        }
        __syncthreads();
    }

    // ---- Routing iters 1,2 (R11-proven all-fp32-after-load form) ----
    const int b2  = tid & 3;
    const int r2  = tid >> 2;
    const int sl3 = r2 & 3;

    #pragma unroll
    for (int it = 1; it < 3; it++) {
        float S[16];
        #pragma unroll
        for (int c = 0; c < 16; c++) S[c] = 0.f;
        float Zp = 0.f;
        float vv[16];
        #pragma unroll
        for (int c = 0; c < 16; c++) vv[c] = vss[b2 * 16 + c];

        #pragma unroll
        for (int rd = 0; rd < NRD; rd++) {
            const int i = rd * 128 + r2;
            const unsigned base = (unsigned)((i * 4 + (b2 ^ sl3)) * 8);
            float xf[16];
            #pragma unroll
            for (int cc = 0; cc < 4; cc++) {
                uint2 u = *reinterpret_cast<const uint2*>(xhb + base + ((cc ^ sl3) * 2));
                __half2 h0 = *reinterpret_cast<__half2*>(&u.x);
                __half2 h1 = *reinterpret_cast<__half2*>(&u.y);
                float2 f0 = __half22float2(h0);
                float2 f1 = __half22float2(h1);
                xf[cc * 4 + 0] = f0.x; xf[cc * 4 + 1] = f0.y;
                xf[cc * 4 + 2] = f1.x; xf[cc * 4 + 3] = f1.y;
            }
            float a = 0.f;
            #pragma unroll
            for (int c = 0; c < 16; c++) a = fmaf(vv[c], xf[c], a);
            float e = __expf(a);           // a IS the logit (vsum . x_hat); |a| small
            Zp += e;
            #pragma unroll
            for (int c = 0; c < 16; c++) S[c] = fmaf(e, xf[c], S[c]);
        }

        #pragma unroll
        for (int m = 4; m < 32; m <<= 1) {
            #pragma unroll
            for (int c = 0; c < 16; c++)
                S[c] += __shfl_xor_sync(0xffffffffu, S[c], m);
            Zp += __shfl_xor_sync(0xffffffffu, Zp, m);
        }
        if (lane < 4) {
            float* rp = red + (warp * 4 + lane) * 17;
            #pragma unroll
            for (int c = 0; c < 16; c++) rp[c] = S[c];
            rp[16] = Zp;
        }
        __syncthreads();

        if (tid < 64) {
            const int bb = tid & 3, c = tid >> 2;
            float s = 0.f;
            #pragma unroll
            for (int w2 = 0; w2 < 16; w2++)
                s += red[(w2 * 4 + bb) * 17 + c];
            tot[bb * 16 + c] = s;
        } else if (tid < 68) {
            const int bb = tid - 64;
            float z = 0.f;
            #pragma unroll
            for (int w2 = 0; w2 < 16; w2++)
                z += red[(w2 * 4 + bb) * 17 + 16];
            zt[bb] = z;
        }
        __syncthreads();

        if (tid < BPC) {
            const int bb = tid;
            float inv = 1.f / zt[bb];
            float sv[16], n2 = 0.f;
            #pragma unroll
            for (int c = 0; c < 16; c++) {
                sv[c] = tot[bb * 16 + c] * inv;
                n2 += sv[c] * sv[c];
            }
            float nr = sqrtf(n2);
            float coef = (n2 / (1.f + n2)) / (nr + 1e-7f);
            #pragma unroll
            for (int c = 0; c < 16; c++) {
                float vn = coef * sv[c];
                vsm[bb * 16 + c] = vn;
                vss[bb * 16 + c] += vn;
            }
        }
        __syncthreads();
    }

    // ---- Output (B, J, C) ----
    if (tid < 64) {
        const int bb = tid >> 4, c = tid & 15;
        out[((size_t)(bg * BPC + bb) * JCAPS + j) * CDIM + c] = vsm[bb * 16 + c];
    }
}

extern "C" void kernel_launch(void* const* d_in, const int* in_sizes, int n_in,
                              void* d_out, int out_size)
{
    const float* x = (const float*)d_in[0];
    const float* W = (const float*)d_in[1];
    if (n_in >= 2 &&
        in_sizes[0] == JCAPS * ICAPS * DDIM * CDIM &&
        in_sizes[1] == BATCH * ICAPS * DDIM) {
        const float* t = x; x = W; W = t;
    }
    float* out = (float*)d_out;

    convert_w_kernel<<<720, 512>>>(W);

    cudaFuncSetAttribute(digitcaps_kernel,
                         cudaFuncAttributeMaxDynamicSharedMemorySize,
                         SMEMF * (int)sizeof(float));
    dim3 grid((BATCH / BPC) * JCAPS);      // 1280 CTAs
    digitcaps_kernel<<<grid, TPB, SMEMF * sizeof(float)>>>(x, out);
}